// round 15
// baseline (speedup 1.0000x reference)
#include <cuda_runtime.h>

#define B_MAX 4096
#define GPB   4      // graphs per prep block (small -> 1024 blocks, occ ~83%)
#define GPF   8      // graphs per final block
#define NSM   148    // sm_103a SMs

// Scratch (device globals — allocation is forbidden). 16B-aligned for float4.
__device__ __align__(16) float g_w[B_MAX * 128];     // per-graph gate vector  w_b = Wk @ q_b
__device__ __align__(16) float g_c[B_MAX];           // per-graph gate bias    c_b = bk . q_b
__device__ __align__(16) float g_xagg[B_MAX * 128];  // gated segment sums

// ---------------------------------------------------------------------------
// Kernel 1: per-graph precompute. GPB=4 graphs/block, 256 threads, 1024 blocks
// (prep was grid-starved at 256 blocks: occ 20.7%, 24.7us).
//   q_b = u_b @ Wq + bq ; w_b = Wk @ q_b ; c_b = bk . q_b ; zero g_xagg.
// ---------------------------------------------------------------------------
__global__ void __launch_bounds__(256)
prep_kernel(const float* __restrict__ u,
            const float* __restrict__ Wk,
            const float* __restrict__ bk,
            const float* __restrict__ Wq,
            const float* __restrict__ bq,
            int B) {
    __shared__ float su[GPB * 128];        // 2 KB
    __shared__ float sq[GPB * 64];         // 1 KB

    const int tid = threadIdx.x;
    const int g0  = blockIdx.x * GPB;

    // load 4 u rows (128 float4, first 128 threads)
    if (tid < GPB * 32) {
        int g = tid >> 5, c = tid & 31;
        if (g0 + g < B)
            ((float4*)su)[tid] = ((const float4*)(u + (size_t)(g0 + g) * 128))[c];
        else
            ((float4*)su)[tid] = make_float4(0.f, 0.f, 0.f, 0.f);
    }
    __syncthreads();

    // q phase: one (g, h) output per thread. 256 threads = 4 graphs x 64 h.
    {
        const int h = tid & 63, g = tid >> 6;
        const float* sg = su + g * 128;
        float a = bq[h];
#pragma unroll 4
        for (int f = 0; f < 128; f++)
            a += sg[f] * Wq[f * 64 + h];   // Wq coalesced across lanes (h)
        sq[g * 64 + h] = a;
    }
    __syncthreads();

    // c phase
    if (tid < GPB && g0 + tid < B) {
        float s = 0.0f;
        const float* qr = sq + tid * 64;
#pragma unroll 8
        for (int h = 0; h < 64; h++) s += bk[h] * qr[h];
        g_c[g0 + tid] = s;
    }

    // w phase: thread = (gp, f); gp owns graphs gp*2, gp*2+1.
    // Wk row f read directly: per-thread contiguous float4 (L1-resident 32KB).
    {
        const int f = tid & 127, gp = tid >> 7;
        const float4* wkrow = (const float4*)(Wk + (size_t)f * 64);
        float a0 = 0.0f, a1 = 0.0f;
#pragma unroll 4
        for (int hq = 0; hq < 16; hq++) {      // 16 float4 = 64 h-values
            const float4 wk4 = __ldg(wkrow + hq);
            const float* q0 = sq + (gp * 2 + 0) * 64 + hq * 4;
            const float* q1 = sq + (gp * 2 + 1) * 64 + hq * 4;
            a0 += q0[0] * wk4.x + q0[1] * wk4.y + q0[2] * wk4.z + q0[3] * wk4.w;
            a1 += q1[0] * wk4.x + q1[1] * wk4.y + q1[2] * wk4.z + q1[3] * wk4.w;
        }
        const int ga = g0 + gp * 2, gb = ga + 1;
        if (ga < B) { g_w[(size_t)ga * 128 + f] = a0; g_xagg[(size_t)ga * 128 + f] = 0.0f; }
        if (gb < B) { g_w[(size_t)gb * 128 + f] = a1; g_xagg[(size_t)gb * 128 + f] = 0.0f; }
    }
}

// ---------------------------------------------------------------------------
// Kernel 2: HBM-bound streaming pass over x (512 MB). One warp per node,
// unrolled x4; w-vector + bias cached in registers across the sorted segment.
// Grid = 148*8 equal-work blocks (the R12 balance win).
// ---------------------------------------------------------------------------
__device__ __forceinline__ float warp_sum(float d) {
    d += __shfl_xor_sync(0xffffffffu, d, 16);
    d += __shfl_xor_sync(0xffffffffu, d, 8);
    d += __shfl_xor_sync(0xffffffffu, d, 4);
    d += __shfl_xor_sync(0xffffffffu, d, 2);
    d += __shfl_xor_sync(0xffffffffu, d, 1);
    return d;
}

__global__ void __launch_bounds__(256)
main_kernel(const float* __restrict__ x,
            const int* __restrict__ batch,
            int N, int chunk) {
    const int warp = threadIdx.x >> 5;
    const int lane = threadIdx.x & 31;
    long start = (long)blockIdx.x * chunk;
    long end   = start + chunk;
    if (end > N) end = N;

    float4 acc = make_float4(0.f, 0.f, 0.f, 0.f);
    float4 wv  = make_float4(0.f, 0.f, 0.f, 0.f);
    float  cb  = 0.0f;
    int    cur = -1;

    long node = start + warp;
    const long lim4 = end - 24;

#define PROC(bi, xi)                                                    \
        if (bi != cur) {                                                \
            if (cur >= 0) {                                             \
                float* p = g_xagg + (size_t)cur * 128 + lane * 4;       \
                atomicAdd(p + 0, acc.x); atomicAdd(p + 1, acc.y);       \
                atomicAdd(p + 2, acc.z); atomicAdd(p + 3, acc.w);       \
            }                                                           \
            acc = make_float4(0.f, 0.f, 0.f, 0.f);                      \
            cur = bi;                                                   \
            wv  = __ldg((const float4*)(g_w + (size_t)bi * 128) + lane);\
            cb  = g_c[bi];                                              \
        }                                                               \
        {                                                               \
            float d = xi.x * wv.x + xi.y * wv.y + xi.z * wv.z + xi.w * wv.w; \
            d = warp_sum(d);                                            \
            const float a = 1.0f / (1.0f + __expf(-(d + cb)));          \
            acc.x += a * xi.x; acc.y += a * xi.y;                       \
            acc.z += a * xi.z; acc.w += a * xi.w;                       \
        }

    for (; node < lim4; node += 32) {
        const int b0 = batch[node]      & (B_MAX - 1);
        const int b1 = batch[node + 8]  & (B_MAX - 1);
        const int b2 = batch[node + 16] & (B_MAX - 1);
        const int b3 = batch[node + 24] & (B_MAX - 1);

        const float4 x0 = __ldcs((const float4*)(x + (size_t)(node)      * 128) + lane);
        const float4 x1 = __ldcs((const float4*)(x + (size_t)(node + 8)  * 128) + lane);
        const float4 x2 = __ldcs((const float4*)(x + (size_t)(node + 16) * 128) + lane);
        const float4 x3 = __ldcs((const float4*)(x + (size_t)(node + 24) * 128) + lane);

        PROC(b0, x0)
        PROC(b1, x1)
        PROC(b2, x2)
        PROC(b3, x3)
    }

    for (; node < end; node += 8) {
        const int b = batch[node] & (B_MAX - 1);
        const float4 xv = __ldcs((const float4*)(x + (size_t)node * 128) + lane);
        PROC(b, xv)
    }
#undef PROC

    if (cur >= 0) {
        float* p = g_xagg + (size_t)cur * 128 + lane * 4;
        atomicAdd(p + 0, acc.x); atomicAdd(p + 1, acc.y);
        atomicAdd(p + 2, acc.z); atomicAdd(p + 3, acc.w);
    }
}

// ---------------------------------------------------------------------------
// Kernel 3: out = concat(x_agg, u) @ Wu + bu.  (best-measured R7 shape)
// 512 threads = (quarter 0..3, j 0..127), split-K x4, GPF=8 -> 512 blocks.
// ---------------------------------------------------------------------------
__global__ void __launch_bounds__(512)
final_kernel(const float* __restrict__ u,
             const float* __restrict__ Wu,
             const float* __restrict__ bu,
             float* __restrict__ out,
             int B) {
    __shared__ __align__(16) float s[GPF * 256];     // 8 KB concat inputs
    __shared__ float spart[3 * GPF * 128];           // 12 KB partials (quarters 1-3)
    const int j       = threadIdx.x & 127;  // output column
    const int quarter = threadIdx.x >> 7;   // 0..3, owns 64 K-values
    const int g0      = blockIdx.x * GPF;

    // stage concat(x_agg, u) rows, float4-vectorized
    for (int idx = threadIdx.x; idx < GPF * 64; idx += 512) {
        int g = idx >> 6, c = idx & 63;   // c: float4 index within 256-float row
        float4 v;
        if (g0 + g < B)
            v = (c < 32) ? ((const float4*)(g_xagg + (size_t)(g0 + g) * 128))[c]
                         : ((const float4*)(u      + (size_t)(g0 + g) * 128))[c - 32];
        else
            v = make_float4(0.f, 0.f, 0.f, 0.f);
        ((float4*)s)[g * 64 + c] = v;
    }
    __syncthreads();

    float acc[GPF];
#pragma unroll
    for (int g = 0; g < GPF; g++) acc[g] = 0.0f;

    const int i0 = quarter * 64;
#pragma unroll
    for (int ii = 0; ii < 64; ii += 8) {
        float wv[8];
#pragma unroll
        for (int t = 0; t < 8; t++)            // 8 independent coalesced LDGs
            wv[t] = Wu[(size_t)(i0 + ii + t) * 128 + j];
#pragma unroll
        for (int g = 0; g < GPF; g++) {
            const float4 sa = *(const float4*)&s[g * 256 + i0 + ii];
            const float4 sb = *(const float4*)&s[g * 256 + i0 + ii + 4];
            acc[g] += sa.x * wv[0] + sa.y * wv[1] + sa.z * wv[2] + sa.w * wv[3]
                    + sb.x * wv[4] + sb.y * wv[5] + sb.z * wv[6] + sb.w * wv[7];
        }
    }

    if (quarter != 0) {
#pragma unroll
        for (int g = 0; g < GPF; g++)
            spart[(quarter - 1) * GPF * 128 + g * 128 + j] = acc[g];
    }
    __syncthreads();
    if (quarter == 0) {
        const float b0 = bu[j];
#pragma unroll
        for (int g = 0; g < GPF; g++)
            if (g0 + g < B)
                out[(size_t)(g0 + g) * 128 + j] =
                    acc[g] + spart[0 * GPF * 128 + g * 128 + j]
                           + spart[1 * GPF * 128 + g * 128 + j]
                           + spart[2 * GPF * 128 + g * 128 + j] + b0;
    }
}

// ---------------------------------------------------------------------------
// Launch
// ---------------------------------------------------------------------------
extern "C" void kernel_launch(void* const* d_in, const int* in_sizes, int n_in,
                              void* d_out, int out_size) {
    const float* x     = (const float*)d_in[0];
    // d_in[1] = edge_index (unused), d_in[2] = e (unused)
    const float* u     = (const float*)d_in[3];
    const int*   batch = (const int*)d_in[4];   // int64 in reference -> int32 on device
    const float* Wk    = (const float*)d_in[5];
    const float* bk    = (const float*)d_in[6];
    const float* Wq    = (const float*)d_in[7];
    const float* bq    = (const float*)d_in[8];
    const float* Wu    = (const float*)d_in[9];
    const float* bu    = (const float*)d_in[10];
    float* out = (float*)d_out;

    const int N = in_sizes[0] / 128;   // 1,000,000
    const int B = out_size / 128;      // 4096

    prep_kernel<<<(B + GPB - 1) / GPB, 256>>>(u, Wk, bk, Wq, bq, B);

    // Equal-work grid: exactly 8 blocks per SM (R12 balance win).
    const int grid  = NSM * 8;                 // 1184
    const int chunk = (N + grid - 1) / grid;   // 845
    main_kernel<<<grid, 256>>>(x, batch, N, chunk);

    final_kernel<<<(B + GPF - 1) / GPF, 512>>>(u, Wu, bu, out, B);
}

// round 16
// speedup vs baseline: 1.0682x; 1.0682x over previous
#include <cuda_runtime.h>

#define B_MAX 4096
#define GPB   16     // graphs per prep block
#define GPF   8      // graphs per final block
#define NSM   148    // sm_103a SMs

// Scratch (device globals — allocation is forbidden). 16B-aligned for float4.
__device__ __align__(16) float g_w[B_MAX * 128];     // per-graph gate vector
__device__ __align__(16) float g_c[B_MAX];           // per-graph gate bias
__device__ __align__(16) float g_xagg[B_MAX * 128];  // gated segment sums
__device__ __align__(16) float g_M[128 * 128];       // M[f'][f] = sum_h Wk[f'][h] Wq[f][h]
__device__ __align__(16) float g_v[128];             // v[f] = sum_h Wq[f][h] bk[h]
__device__ __align__(16) float g_wkbq[128];          // (Wk bq)[f']
__device__ float g_c0;                               // bk . bq

// ---------------------------------------------------------------------------
// Kernel 0: precompute M, v, wkbq, c0.  128 blocks x 128 threads, ~1M FMA.
//   block = f' (row of M), thread = f (col of M).
// ---------------------------------------------------------------------------
__global__ void __launch_bounds__(128)
precomp_kernel(const float* __restrict__ Wk,
               const float* __restrict__ bk,
               const float* __restrict__ Wq,
               const float* __restrict__ bq) {
    __shared__ float sWk[64];
    const int fp = blockIdx.x;    // f' 0..127
    const int f  = threadIdx.x;   // f  0..127

    if (f < 64) sWk[f] = Wk[fp * 64 + f];
    __syncthreads();

    // M[f'][f] = dot(Wk row f', Wq row f) over h
    {
        float s = 0.0f;
        const float4* wqr = (const float4*)(Wq + (size_t)f * 64);
#pragma unroll
        for (int hq = 0; hq < 16; hq++) {
            const float4 w4 = __ldg(wqr + hq);
            s += w4.x * sWk[hq * 4 + 0] + w4.y * sWk[hq * 4 + 1]
               + w4.z * sWk[hq * 4 + 2] + w4.w * sWk[hq * 4 + 3];
        }
        g_M[(size_t)fp * 128 + f] = s;
    }

    // wkbq[f'] (one thread per block)
    if (f == 0) {
        float t = 0.0f;
#pragma unroll 8
        for (int h = 0; h < 64; h++) t += sWk[h] * bq[h];
        g_wkbq[fp] = t;
    }

    // block 0: v[f] = dot(Wq row f, bk); c0 = bk.bq
    if (fp == 0) {
        float t = 0.0f;
        const float* wq = Wq + (size_t)f * 64;
#pragma unroll 8
        for (int h = 0; h < 64; h++) t += wq[h] * bk[h];
        g_v[f] = t;
        if (f == 0) {
            float c = 0.0f;
#pragma unroll 8
            for (int h = 0; h < 64; h++) c += bk[h] * bq[h];
            g_c0 = c;
        }
    }
}

// ---------------------------------------------------------------------------
// Kernel 1: per-graph precompute, single phase (q-phase eliminated via M).
//   w_b = M u_b + wkbq ; c_b = v . u_b + c0 ; zero g_xagg.
// 16 graphs/block, 256 threads: thread = (q8, f'), 8 graphs each, 8-acc ILP.
// M row f' per-thread contiguous (64 KB, L1-resident). smem reads = LDS.128.
// ---------------------------------------------------------------------------
__global__ void __launch_bounds__(256)
prep_kernel(const float* __restrict__ u, int B) {
    __shared__ __align__(16) float su[GPB * 128];   // 8 KB
    const int tid = threadIdx.x;
    const int g0  = blockIdx.x * GPB;

    for (int i = tid; i < GPB * 32; i += 256) {
        int g = i >> 5, c = i & 31;
        if (g0 + g < B)
            ((float4*)su)[i] = ((const float4*)(u + (size_t)(g0 + g) * 128))[c];
        else
            ((float4*)su)[i] = make_float4(0.f, 0.f, 0.f, 0.f);
    }
    __syncthreads();

    // c phase: 16 threads, one graph each
    if (tid < GPB && g0 + tid < B) {
        float s = g_c0;
        const float* ur = su + tid * 128;
#pragma unroll 8
        for (int f = 0; f < 128; f++) s += g_v[f] * ur[f];
        g_c[g0 + tid] = s;
    }

    // w phase: thread = (q8, f'); q8 owns graphs q8*8..q8*8+7, 128-deep dot
    {
        const int f = tid & 127, q8 = tid >> 7;
        const float4* Mrow = (const float4*)(g_M + (size_t)f * 128);
        const float wb = g_wkbq[f];
        float acc[8];
#pragma unroll
        for (int j = 0; j < 8; j++) acc[j] = 0.0f;
#pragma unroll 4
        for (int fq = 0; fq < 32; fq++) {       // 32 float4 = 128 f-values
            const float4 m4 = __ldg(Mrow + fq);
#pragma unroll
            for (int j = 0; j < 8; j++) {
                const float4 u4 = *(const float4*)(su + (q8 * 8 + j) * 128 + fq * 4);
                acc[j] += u4.x * m4.x + u4.y * m4.y + u4.z * m4.z + u4.w * m4.w;
            }
        }
#pragma unroll
        for (int j = 0; j < 8; j++) {
            const int g = g0 + q8 * 8 + j;
            if (g < B) {
                g_w[(size_t)g * 128 + f]    = acc[j] + wb;
                g_xagg[(size_t)g * 128 + f] = 0.0f;
            }
        }
    }
}

// ---------------------------------------------------------------------------
// Kernel 2: HBM-bound streaming pass over x (512 MB). One warp per node,
// unrolled x4; w-vector + bias cached in registers across the sorted segment.
// Grid = 148*8 equal-work blocks (the R12 balance win).
// ---------------------------------------------------------------------------
__device__ __forceinline__ float warp_sum(float d) {
    d += __shfl_xor_sync(0xffffffffu, d, 16);
    d += __shfl_xor_sync(0xffffffffu, d, 8);
    d += __shfl_xor_sync(0xffffffffu, d, 4);
    d += __shfl_xor_sync(0xffffffffu, d, 2);
    d += __shfl_xor_sync(0xffffffffu, d, 1);
    return d;
}

__global__ void __launch_bounds__(256)
main_kernel(const float* __restrict__ x,
            const int* __restrict__ batch,
            int N, int chunk) {
    const int warp = threadIdx.x >> 5;
    const int lane = threadIdx.x & 31;
    long start = (long)blockIdx.x * chunk;
    long end   = start + chunk;
    if (end > N) end = N;

    float4 acc = make_float4(0.f, 0.f, 0.f, 0.f);
    float4 wv  = make_float4(0.f, 0.f, 0.f, 0.f);
    float  cb  = 0.0f;
    int    cur = -1;

    long node = start + warp;
    const long lim4 = end - 24;

#define PROC(bi, xi)                                                    \
        if (bi != cur) {                                                \
            if (cur >= 0) {                                             \
                float* p = g_xagg + (size_t)cur * 128 + lane * 4;       \
                atomicAdd(p + 0, acc.x); atomicAdd(p + 1, acc.y);       \
                atomicAdd(p + 2, acc.z); atomicAdd(p + 3, acc.w);       \
            }                                                           \
            acc = make_float4(0.f, 0.f, 0.f, 0.f);                      \
            cur = bi;                                                   \
            wv  = __ldg((const float4*)(g_w + (size_t)bi * 128) + lane);\
            cb  = g_c[bi];                                              \
        }                                                               \
        {                                                               \
            float d = xi.x * wv.x + xi.y * wv.y + xi.z * wv.z + xi.w * wv.w; \
            d = warp_sum(d);                                            \
            const float a = 1.0f / (1.0f + __expf(-(d + cb)));          \
            acc.x += a * xi.x; acc.y += a * xi.y;                       \
            acc.z += a * xi.z; acc.w += a * xi.w;                       \
        }

    for (; node < lim4; node += 32) {
        const int b0 = batch[node]      & (B_MAX - 1);
        const int b1 = batch[node + 8]  & (B_MAX - 1);
        const int b2 = batch[node + 16] & (B_MAX - 1);
        const int b3 = batch[node + 24] & (B_MAX - 1);

        const float4 x0 = __ldcs((const float4*)(x + (size_t)(node)      * 128) + lane);
        const float4 x1 = __ldcs((const float4*)(x + (size_t)(node + 8)  * 128) + lane);
        const float4 x2 = __ldcs((const float4*)(x + (size_t)(node + 16) * 128) + lane);
        const float4 x3 = __ldcs((const float4*)(x + (size_t)(node + 24) * 128) + lane);

        PROC(b0, x0)
        PROC(b1, x1)
        PROC(b2, x2)
        PROC(b3, x3)
    }

    for (; node < end; node += 8) {
        const int b = batch[node] & (B_MAX - 1);
        const float4 xv = __ldcs((const float4*)(x + (size_t)node * 128) + lane);
        PROC(b, xv)
    }
#undef PROC

    if (cur >= 0) {
        float* p = g_xagg + (size_t)cur * 128 + lane * 4;
        atomicAdd(p + 0, acc.x); atomicAdd(p + 1, acc.y);
        atomicAdd(p + 2, acc.z); atomicAdd(p + 3, acc.w);
    }
}

// ---------------------------------------------------------------------------
// Kernel 3: out = concat(x_agg, u) @ Wu + bu.  (best-measured R7 shape)
// 512 threads = (quarter 0..3, j 0..127), split-K x4, GPF=8 -> 512 blocks.
// ---------------------------------------------------------------------------
__global__ void __launch_bounds__(512)
final_kernel(const float* __restrict__ u,
             const float* __restrict__ Wu,
             const float* __restrict__ bu,
             float* __restrict__ out,
             int B) {
    __shared__ __align__(16) float s[GPF * 256];     // 8 KB concat inputs
    __shared__ float spart[3 * GPF * 128];           // 12 KB partials (quarters 1-3)
    const int j       = threadIdx.x & 127;  // output column
    const int quarter = threadIdx.x >> 7;   // 0..3, owns 64 K-values
    const int g0      = blockIdx.x * GPF;

    // stage concat(x_agg, u) rows, float4-vectorized
    for (int idx = threadIdx.x; idx < GPF * 64; idx += 512) {
        int g = idx >> 6, c = idx & 63;   // c: float4 index within 256-float row
        float4 v;
        if (g0 + g < B)
            v = (c < 32) ? ((const float4*)(g_xagg + (size_t)(g0 + g) * 128))[c]
                         : ((const float4*)(u      + (size_t)(g0 + g) * 128))[c - 32];
        else
            v = make_float4(0.f, 0.f, 0.f, 0.f);
        ((float4*)s)[g * 64 + c] = v;
    }
    __syncthreads();

    float acc[GPF];
#pragma unroll
    for (int g = 0; g < GPF; g++) acc[g] = 0.0f;

    const int i0 = quarter * 64;
#pragma unroll
    for (int ii = 0; ii < 64; ii += 8) {
        float wv[8];
#pragma unroll
        for (int t = 0; t < 8; t++)            // 8 independent coalesced LDGs
            wv[t] = Wu[(size_t)(i0 + ii + t) * 128 + j];
#pragma unroll
        for (int g = 0; g < GPF; g++) {
            const float4 sa = *(const float4*)&s[g * 256 + i0 + ii];
            const float4 sb = *(const float4*)&s[g * 256 + i0 + ii + 4];
            acc[g] += sa.x * wv[0] + sa.y * wv[1] + sa.z * wv[2] + sa.w * wv[3]
                    + sb.x * wv[4] + sb.y * wv[5] + sb.z * wv[6] + sb.w * wv[7];
        }
    }

    if (quarter != 0) {
#pragma unroll
        for (int g = 0; g < GPF; g++)
            spart[(quarter - 1) * GPF * 128 + g * 128 + j] = acc[g];
    }
    __syncthreads();
    if (quarter == 0) {
        const float b0 = bu[j];
#pragma unroll
        for (int g = 0; g < GPF; g++)
            if (g0 + g < B)
                out[(size_t)(g0 + g) * 128 + j] =
                    acc[g] + spart[0 * GPF * 128 + g * 128 + j]
                           + spart[1 * GPF * 128 + g * 128 + j]
                           + spart[2 * GPF * 128 + g * 128 + j] + b0;
    }
}

// ---------------------------------------------------------------------------
// Launch
// ---------------------------------------------------------------------------
extern "C" void kernel_launch(void* const* d_in, const int* in_sizes, int n_in,
                              void* d_out, int out_size) {
    const float* x     = (const float*)d_in[0];
    // d_in[1] = edge_index (unused), d_in[2] = e (unused)
    const float* u     = (const float*)d_in[3];
    const int*   batch = (const int*)d_in[4];   // int64 in reference -> int32 on device
    const float* Wk    = (const float*)d_in[5];
    const float* bk    = (const float*)d_in[6];
    const float* Wq    = (const float*)d_in[7];
    const float* bq    = (const float*)d_in[8];
    const float* Wu    = (const float*)d_in[9];
    const float* bu    = (const float*)d_in[10];
    float* out = (float*)d_out;

    const int N = in_sizes[0] / 128;   // 1,000,000
    const int B = out_size / 128;      // 4096

    precomp_kernel<<<128, 128>>>(Wk, bk, Wq, bq);
    prep_kernel<<<(B + GPB - 1) / GPB, 256>>>(u, B);

    // Equal-work grid: exactly 8 blocks per SM (R12 balance win).
    const int grid  = NSM * 8;                 // 1184
    const int chunk = (N + grid - 1) / grid;   // 845
    main_kernel<<<grid, 256>>>(x, batch, N, chunk);

    final_kernel<<<(B + GPF - 1) / GPF, 512>>>(u, Wu, bu, out, B);
}

// round 17
// speedup vs baseline: 1.1694x; 1.0947x over previous
#include <cuda_runtime.h>

#define B_MAX 4096
#define GPB   16     // graphs per prep block
#define GPF   8      // graphs per final block
#define NSM   148    // sm_103a SMs

// Scratch (device globals — allocation is forbidden). 16B-aligned for float4.
__device__ __align__(16) float g_w[B_MAX * 128];     // per-graph gate vector  w_b = Wk @ q_b
__device__ __align__(16) float g_c[B_MAX];           // per-graph gate bias    c_b = bk . q_b
__device__ __align__(16) float g_xagg[B_MAX * 128];  // gated segment sums

// ---------------------------------------------------------------------------
// Kernel 1: per-graph precompute.
//   q_b = u_b @ Wq + bq ; w_b = Wk @ q_b ; c_b = bk . q_b ; zero g_xagg.
// Wq staged in smem (32 KB, coalesced preload, conflict-free reads) — kills
// the q-phase's exposed L2 latency that dominated the 24.7us measurement.
// ---------------------------------------------------------------------------
__global__ void __launch_bounds__(256)
prep_kernel(const float* __restrict__ u,
            const float* __restrict__ Wk,
            const float* __restrict__ bk,
            const float* __restrict__ Wq,
            const float* __restrict__ bq,
            int B) {
    __shared__ float su[GPB * 128];          // 8 KB
    __shared__ float sq[GPB * 64];           // 4 KB
    __shared__ __align__(16) float sWq[128 * 64];  // 32 KB, same [f][h] layout

    const int tid = threadIdx.x;
    const int g0  = blockIdx.x * GPB;

    // coalesced preloads: u rows + full Wq
    for (int i = tid; i < GPB * 32; i += 256) {
        int g = i >> 5, c = i & 31;
        ((float4*)su)[i] = ((const float4*)(u + (size_t)(g0 + g) * 128))[c];
    }
    for (int i = tid; i < 2048; i += 256)    // 2048 float4 = 32 KB
        ((float4*)sWq)[i] = ((const float4*)Wq)[i];
    __syncthreads();

    // q phase: thread = (gq, h); gq owns graphs gq*4..gq*4+3.
    // sWq[f*64+h]: lanes vary h (consecutive) -> conflict-free LDS.
    {
        const int h = tid & 63, gq = tid >> 6;
        const float* s0 = su + (gq * 4 + 0) * 128;
        const float* s1 = su + (gq * 4 + 1) * 128;
        const float* s2 = su + (gq * 4 + 2) * 128;
        const float* s3 = su + (gq * 4 + 3) * 128;
        float a0 = bq[h], a1 = a0, a2 = a0, a3 = a0;
#pragma unroll 4
        for (int f = 0; f < 128; f++) {
            const float wq = sWq[f * 64 + h];
            a0 += s0[f] * wq;                  // smem broadcast
            a1 += s1[f] * wq;
            a2 += s2[f] * wq;
            a3 += s3[f] * wq;
        }
        sq[(gq * 4 + 0) * 64 + h] = a0;
        sq[(gq * 4 + 1) * 64 + h] = a1;
        sq[(gq * 4 + 2) * 64 + h] = a2;
        sq[(gq * 4 + 3) * 64 + h] = a3;
    }
    __syncthreads();

    // c phase
    if (tid < GPB && g0 + tid < B) {
        float s = 0.0f;
        const float* qr = sq + tid * 64;
#pragma unroll 8
        for (int h = 0; h < 64; h++) s += bk[h] * qr[h];
        g_c[g0 + tid] = s;
    }

    // w phase: thread = (q8, f); q8 owns graphs q8*8..q8*8+7.
    // Wk row f read directly: per-thread contiguous float4 (L1-resident 32KB).
    {
        const int f = tid & 127, q8 = tid >> 7;
        const float4* wkrow = (const float4*)(Wk + (size_t)f * 64);
        float acc[8];
#pragma unroll
        for (int j = 0; j < 8; j++) acc[j] = 0.0f;
#pragma unroll 4
        for (int hq = 0; hq < 16; hq++) {      // 16 float4 = 64 h-values
            const float4 wk4 = __ldg(wkrow + hq);
            const int h = hq * 4;
#pragma unroll
            for (int j = 0; j < 8; j++) {
                const float* qj = sq + (q8 * 8 + j) * 64 + h;
                acc[j] += qj[0] * wk4.x + qj[1] * wk4.y
                        + qj[2] * wk4.z + qj[3] * wk4.w;
            }
        }
#pragma unroll
        for (int j = 0; j < 8; j++) {
            const int g = g0 + q8 * 8 + j;
            if (g < B) {
                g_w[(size_t)g * 128 + f]    = acc[j];
                g_xagg[(size_t)g * 128 + f] = 0.0f;
            }
        }
    }
}

// ---------------------------------------------------------------------------
// Kernel 2: HBM-bound streaming pass over x (512 MB). One warp per node,
// unrolled x4; w-vector + bias cached in registers across the sorted segment.
// Grid = 148*8 equal-work blocks (the R12 balance win).
// ---------------------------------------------------------------------------
__device__ __forceinline__ float warp_sum(float d) {
    d += __shfl_xor_sync(0xffffffffu, d, 16);
    d += __shfl_xor_sync(0xffffffffu, d, 8);
    d += __shfl_xor_sync(0xffffffffu, d, 4);
    d += __shfl_xor_sync(0xffffffffu, d, 2);
    d += __shfl_xor_sync(0xffffffffu, d, 1);
    return d;
}

__global__ void __launch_bounds__(256)
main_kernel(const float* __restrict__ x,
            const int* __restrict__ batch,
            int N, int chunk) {
    const int warp = threadIdx.x >> 5;
    const int lane = threadIdx.x & 31;
    long start = (long)blockIdx.x * chunk;
    long end   = start + chunk;
    if (end > N) end = N;

    float4 acc = make_float4(0.f, 0.f, 0.f, 0.f);
    float4 wv  = make_float4(0.f, 0.f, 0.f, 0.f);
    float  cb  = 0.0f;
    int    cur = -1;

    long node = start + warp;
    const long lim4 = end - 24;

#define PROC(bi, xi)                                                    \
        if (bi != cur) {                                                \
            if (cur >= 0) {                                             \
                float* p = g_xagg + (size_t)cur * 128 + lane * 4;       \
                atomicAdd(p + 0, acc.x); atomicAdd(p + 1, acc.y);       \
                atomicAdd(p + 2, acc.z); atomicAdd(p + 3, acc.w);       \
            }                                                           \
            acc = make_float4(0.f, 0.f, 0.f, 0.f);                      \
            cur = bi;                                                   \
            wv  = __ldg((const float4*)(g_w + (size_t)bi * 128) + lane);\
            cb  = g_c[bi];                                              \
        }                                                               \
        {                                                               \
            float d = xi.x * wv.x + xi.y * wv.y + xi.z * wv.z + xi.w * wv.w; \
            d = warp_sum(d);                                            \
            const float a = 1.0f / (1.0f + __expf(-(d + cb)));          \
            acc.x += a * xi.x; acc.y += a * xi.y;                       \
            acc.z += a * xi.z; acc.w += a * xi.w;                       \
        }

    for (; node < lim4; node += 32) {
        const int b0 = batch[node]      & (B_MAX - 1);
        const int b1 = batch[node + 8]  & (B_MAX - 1);
        const int b2 = batch[node + 16] & (B_MAX - 1);
        const int b3 = batch[node + 24] & (B_MAX - 1);

        const float4 x0 = __ldcs((const float4*)(x + (size_t)(node)      * 128) + lane);
        const float4 x1 = __ldcs((const float4*)(x + (size_t)(node + 8)  * 128) + lane);
        const float4 x2 = __ldcs((const float4*)(x + (size_t)(node + 16) * 128) + lane);
        const float4 x3 = __ldcs((const float4*)(x + (size_t)(node + 24) * 128) + lane);

        PROC(b0, x0)
        PROC(b1, x1)
        PROC(b2, x2)
        PROC(b3, x3)
    }

    for (; node < end; node += 8) {
        const int b = batch[node] & (B_MAX - 1);
        const float4 xv = __ldcs((const float4*)(x + (size_t)node * 128) + lane);
        PROC(b, xv)
    }
#undef PROC

    if (cur >= 0) {
        float* p = g_xagg + (size_t)cur * 128 + lane * 4;
        atomicAdd(p + 0, acc.x); atomicAdd(p + 1, acc.y);
        atomicAdd(p + 2, acc.z); atomicAdd(p + 3, acc.w);
    }
}

// ---------------------------------------------------------------------------
// Kernel 3: out = concat(x_agg, u) @ Wu + bu.  (best-measured R7 shape)
// 512 threads = (quarter 0..3, j 0..127), split-K x4, GPF=8 -> 512 blocks.
// ---------------------------------------------------------------------------
__global__ void __launch_bounds__(512)
final_kernel(const float* __restrict__ u,
             const float* __restrict__ Wu,
             const float* __restrict__ bu,
             float* __restrict__ out,
             int B) {
    __shared__ __align__(16) float s[GPF * 256];     // 8 KB concat inputs
    __shared__ float spart[3 * GPF * 128];           // 12 KB partials (quarters 1-3)
    const int j       = threadIdx.x & 127;  // output column
    const int quarter = threadIdx.x >> 7;   // 0..3, owns 64 K-values
    const int g0      = blockIdx.x * GPF;

    // stage concat(x_agg, u) rows, float4-vectorized
    for (int idx = threadIdx.x; idx < GPF * 64; idx += 512) {
        int g = idx >> 6, c = idx & 63;   // c: float4 index within 256-float row
        float4 v;
        if (g0 + g < B)
            v = (c < 32) ? ((const float4*)(g_xagg + (size_t)(g0 + g) * 128))[c]
                         : ((const float4*)(u      + (size_t)(g0 + g) * 128))[c - 32];
        else
            v = make_float4(0.f, 0.f, 0.f, 0.f);
        ((float4*)s)[g * 64 + c] = v;
    }
    __syncthreads();

    float acc[GPF];
#pragma unroll
    for (int g = 0; g < GPF; g++) acc[g] = 0.0f;

    const int i0 = quarter * 64;
#pragma unroll
    for (int ii = 0; ii < 64; ii += 8) {
        float wv[8];
#pragma unroll
        for (int t = 0; t < 8; t++)            // 8 independent coalesced LDGs
            wv[t] = Wu[(size_t)(i0 + ii + t) * 128 + j];
#pragma unroll
        for (int g = 0; g < GPF; g++) {
            const float4 sa = *(const float4*)&s[g * 256 + i0 + ii];
            const float4 sb = *(const float4*)&s[g * 256 + i0 + ii + 4];
            acc[g] += sa.x * wv[0] + sa.y * wv[1] + sa.z * wv[2] + sa.w * wv[3]
                    + sb.x * wv[4] + sb.y * wv[5] + sb.z * wv[6] + sb.w * wv[7];
        }
    }

    if (quarter != 0) {
#pragma unroll
        for (int g = 0; g < GPF; g++)
            spart[(quarter - 1) * GPF * 128 + g * 128 + j] = acc[g];
    }
    __syncthreads();
    if (quarter == 0) {
        const float b0 = bu[j];
#pragma unroll
        for (int g = 0; g < GPF; g++)
            if (g0 + g < B)
                out[(size_t)(g0 + g) * 128 + j] =
                    acc[g] + spart[0 * GPF * 128 + g * 128 + j]
                           + spart[1 * GPF * 128 + g * 128 + j]
                           + spart[2 * GPF * 128 + g * 128 + j] + b0;
    }
}

// ---------------------------------------------------------------------------
// Launch
// ---------------------------------------------------------------------------
extern "C" void kernel_launch(void* const* d_in, const int* in_sizes, int n_in,
                              void* d_out, int out_size) {
    const float* x     = (const float*)d_in[0];
    // d_in[1] = edge_index (unused), d_in[2] = e (unused)
    const float* u     = (const float*)d_in[3];
    const int*   batch = (const int*)d_in[4];   // int64 in reference -> int32 on device
    const float* Wk    = (const float*)d_in[5];
    const float* bk    = (const float*)d_in[6];
    const float* Wq    = (const float*)d_in[7];
    const float* bq    = (const float*)d_in[8];
    const float* Wu    = (const float*)d_in[9];
    const float* bu    = (const float*)d_in[10];
    float* out = (float*)d_out;

    const int N = in_sizes[0] / 128;   // 1,000,000
    const int B = out_size / 128;      // 4096

    prep_kernel<<<(B + GPB - 1) / GPB, 256>>>(u, Wk, bk, Wq, bq, B);

    // Equal-work grid: exactly 8 blocks per SM (R12 balance win).
    const int grid  = NSM * 8;                 // 1184
    const int chunk = (N + grid - 1) / grid;   // 845
    main_kernel<<<grid, 256>>>(x, batch, N, chunk);

    final_kernel<<<(B + GPF - 1) / GPF, 512>>>(u, Wu, bu, out, B);
}